// round 8
// baseline (speedup 1.0000x reference)
#include <cuda_runtime.h>
#include <cuda_bf16.h>
#include <cstdint>

#define BSZ 512
#define DIM 128
#define MARGIN 0.2f
#define APB 4                 // anchors per block
#define NBLK (BSZ / APB)      // 128 blocks

// Scratch (no allocations anywhere)
__device__ float g_psum[BSZ];
__device__ int   g_pcnt[BSZ];
__device__ int   g_ctr;       // zero-init; last block resets -> replay-safe

typedef unsigned long long ull;

// ---- packed f32x2 helpers (Blackwell) -------------------------------------
__device__ __forceinline__ ull add2(ull a, ull b) {
    ull r; asm("add.rn.f32x2 %0, %1, %2;" : "=l"(r) : "l"(a), "l"(b)); return r;
}
__device__ __forceinline__ ull fma2(ull a, ull b, ull c) {
    ull r; asm("fma.rn.f32x2 %0, %1, %2, %3;" : "=l"(r) : "l"(a), "l"(b), "l"(c)); return r;
}
__device__ __forceinline__ float sum2(ull v) {
    float lo, hi;
    asm("mov.b64 {%0, %1}, %2;" : "=f"(lo), "=f"(hi) : "l"(v));
    return lo + hi;
}

// ---------------------------------------------------------------------------
// ONE fused kernel: per block, compute 4 full distance rows (diff-based,
// matching reference sum((a-b)^2)), mine them, and reduce via atomic-counter
// last-block (deterministic fixed-order).
// ---------------------------------------------------------------------------
__global__ __launch_bounds__(256, 2)
void fused_kernel(const float* __restrict__ emb,
                  const int* __restrict__ labels,
                  float* __restrict__ out) {
    __shared__ __align__(16) float sA[APB][DIM];   // NEGATED anchor rows
    __shared__ __align__(16) float sd[APB][BSZ];   // distance rows (8KB)
    __shared__ int sLast;

    const int tid  = threadIdx.x;
    const int warp = tid >> 5;
    const int lane = tid & 31;
    const int i0   = blockIdx.x * APB;

    // ---- load negated anchors (4 rows x 32 float4; threads 0..127) ----
    if (tid < 128) {
        const int a  = tid >> 5;
        const int d4 = tid & 31;
        const float4 v = *(const float4*)(emb + (size_t)(i0 + a) * DIM + d4 * 4);
        *(float4*)&sA[a][d4 * 4] = make_float4(-v.x, -v.y, -v.z, -v.w);
    }
    __syncthreads();

    // ---- phase 1: distances. warp w covers j in [w*64, w*64+64);
    //      lane owns j_lo = w*64+lane and j_hi = j_lo+32. ----
    const int jlo = warp * 64 + lane;
    const int jhi = jlo + 32;
    const ulonglong2* b0p = (const ulonglong2*)(emb + (size_t)jlo * DIM);
    const ulonglong2* b1p = (const ulonglong2*)(emb + (size_t)jhi * DIM);

    ull acc0[APB], acc1[APB];
    #pragma unroll
    for (int a = 0; a < APB; a++) { acc0[a] = 0ull; acc1[a] = 0ull; }

    #pragma unroll 8
    for (int d4 = 0; d4 < 32; d4++) {
        const ulonglong2 b0 = __ldg(b0p + d4);
        const ulonglong2 b1 = __ldg(b1p + d4);
        #pragma unroll
        for (int a = 0; a < APB; a++) {
            const ulonglong2 av = *(const ulonglong2*)&sA[a][d4 * 4];
            ull t;
            t = add2(b0.x, av.x); acc0[a] = fma2(t, t, acc0[a]);
            t = add2(b0.y, av.y); acc0[a] = fma2(t, t, acc0[a]);
            t = add2(b1.x, av.x); acc1[a] = fma2(t, t, acc1[a]);
            t = add2(b1.y, av.y); acc1[a] = fma2(t, t, acc1[a]);
        }
    }
    #pragma unroll
    for (int a = 0; a < APB; a++) {
        const float s0 = sum2(acc0[a]);
        const float s1 = sum2(acc1[a]);
        sd[a][jlo] = s0 > 0.f ? sqrtf(s0) : 0.f;
        sd[a][jhi] = s1 > 0.f ? sqrtf(s1) : 0.f;
    }
    __syncthreads();

    // ---- phase 2: mining. warps 0..3, warp w mines row i = i0 + w. ----
    if (warp < APB) {
        const int w = warp;
        const int i = i0 + w;
        const int li = __ldg(labels + i);

        // neg ballot words; lane q holds word q
        unsigned myneg = 0;
        #pragma unroll
        for (int q = 0; q < 16; q++) {
            const int lab = __ldg(labels + q * 32 + lane);
            const unsigned b = __ballot_sync(0xffffffffu, lab != li);
            if (lane == q) myneg = b;
        }

        // positive & (p>i) words; valid-pair count
        unsigned myposgt = 0;
        if (lane < 16) {
            const int r = i - lane * 32;
            const unsigned gt = (r < 0) ? 0xffffffffu
                              : (r >= 31 ? 0u : (0xffffffffu << (r + 1)));
            myposgt = (~myneg) & gt;
        }
        const int cnt = __reduce_add_sync(0xffffffffu,
                                          (lane < 16) ? __popc(myposgt) : 0);

        // exclusive prefix of per-word negative counts (shuffle scan)
        int spf;
        {
            const int nc = (lane < 16) ? __popc(myneg) : 0;
            int incl = nc;
            #pragma unroll
            for (int d = 1; d < 16; d <<= 1) {
                const int t = __shfl_up_sync(0xffffffffu, incl, d);
                if (lane >= d) incl += t;
            }
            spf = incl - nc;
        }

        // fallback j0 = first negative index (argmax over all-False == 0)
        int j0 = 0;
        {
            const unsigned negany =
                __ballot_sync(0xffffffffu, lane < 16 && myneg != 0);
            if (negany) {
                const int c0 = __ffs(negany) - 1;
                const unsigned w0 = __shfl_sync(0xffffffffu, myneg, c0);
                j0 = c0 * 32 + (__ffs(w0) - 1);
            }
        }
        const float dfb = sd[w][j0];

        unsigned pmask16 = __ballot_sync(0xffffffffu, lane < 16 && myposgt != 0);

        float psum = 0.f;
        while (pmask16) {                 // words containing positives
            const int c = __ffs(pmask16) - 1;
            pmask16 &= pmask16 - 1;
            unsigned pm = __shfl_sync(0xffffffffu, myposgt, c);  // uniform
            while (pm) {
                const int b = __ffs(pm) - 1;
                pm &= pm - 1;
                const int p = c * 32 + b;
                const float dap = sd[w][p];
                const float hi  = dap + MARGIN;
                int minj = -1;
                #pragma unroll 1
                for (int q = 0; q < 16; q++) {     // warp-uniform early exit
                    const unsigned nw = __shfl_sync(0xffffffffu, myneg, q);
                    const float dj = sd[w][q * 32 + lane];
                    const bool hit = ((nw >> lane) & 1u) && dj > dap && dj < hi;
                    const unsigned bm = __ballot_sync(0xffffffffu, hit);
                    if (bm) { minj = q * 32 + (__ffs(bm) - 1); break; }
                }
                float dan;
                if (minj >= 0) {
                    const int mc = minj >> 5, mb = minj & 31;
                    const int base = __shfl_sync(0xffffffffu, spf, mc);
                    const unsigned nw = __shfl_sync(0xffffffffu, myneg, mc);
                    const int rank = base + __popc(nw & ((1u << mb) - 1u));
                    dan = sd[w][rank];    // reference quirk: index by neg-rank
                } else {
                    dan = dfb;
                }
                const float v = fmaf(dap, dap, MARGIN) - dan * dan;
                psum += v > 0.f ? v : 0.f;   // uniform across lanes
            }
        }

        if (lane == 0) {
            g_psum[i] = psum;
            g_pcnt[i] = cnt;
            __threadfence();
        }
    }
    __syncthreads();

    // ---- phase 3: last-block deterministic finalize ----
    if (tid == 0) {
        const int prev = atomicAdd(&g_ctr, 1);
        sLast = (prev == NBLK - 1) ? 1 : 0;
    }
    __syncthreads();

    if (sLast) {
        __threadfence();
        __shared__ float rs[256];
        __shared__ int   rc[256];
        rs[tid] = g_psum[tid] + g_psum[tid + 256];
        rc[tid] = g_pcnt[tid] + g_pcnt[tid + 256];
        __syncthreads();
        #pragma unroll
        for (int s = 128; s > 0; s >>= 1) {
            if (tid < s) { rs[tid] += rs[tid + s]; rc[tid] += rc[tid + s]; }
            __syncthreads();
        }
        if (tid == 0) {
            out[0] = rs[0] / (float)rc[0];
            g_ctr  = 0;                    // reset for next graph replay
        }
    }
}

// ---------------------------------------------------------------------------
extern "C" void kernel_launch(void* const* d_in, const int* in_sizes, int n_in,
                              void* d_out, int out_size) {
    const float* emb    = (const float*)d_in[0];
    const int*   labels = (const int*)d_in[1];
    float*       out    = (float*)d_out;

    fused_kernel<<<NBLK, 256>>>(emb, labels, out);
}